// round 1
// baseline (speedup 1.0000x reference)
#include <cuda_runtime.h>
#include <cuda_bf16.h>

// Problem constants (fixed by the dataset)
#define NN 100000
#define EE 1600000
#define DD 128
#define CC 40
#define NBLK 98          // ceil(NN/1024)
#define LN_EPS 1e-5f

// ---------------- device scratch (no allocations allowed) ----------------
__device__ int   g_cnt[NN];
__device__ int   g_fill[NN];
__device__ int   g_rptr[NN + 1];
__device__ int   g_bsum[NBLK];
__device__ int   g_boff[NBLK];
__device__ int   g_cols[EE];
__device__ float g_dinv[NN];
__device__ float g_bufA[NN * CC + 64];
__device__ float g_bufB[NN * CC + 64];

// ---------------- CSR build ----------------
__global__ void zero_kernel() {
    int i = blockIdx.x * blockDim.x + threadIdx.x;
    if (i < NN) { g_cnt[i] = 0; g_fill[i] = 0; }
}

__global__ void hist_kernel(const int* __restrict__ row) {
    int i = blockIdx.x * blockDim.x + threadIdx.x;
    if (i < EE) atomicAdd(&g_cnt[row[i]], 1);
}

// per-1024-chunk exclusive scan; also computes dinv = rsqrt(deg+1)
__global__ void scan1_kernel() {
    __shared__ int sd[1024];
    int t = threadIdx.x;
    int i = blockIdx.x * 1024 + t;
    int v = (i < NN) ? g_cnt[i] : 0;
    sd[t] = v;
    __syncthreads();
    #pragma unroll
    for (int off = 1; off < 1024; off <<= 1) {
        int x = (t >= off) ? sd[t - off] : 0;
        __syncthreads();
        if (t >= off) sd[t] += x;
        __syncthreads();
    }
    if (i < NN) {
        g_rptr[i] = sd[t] - v;                       // local exclusive
        g_dinv[i] = rsqrtf((float)v + 1.0f);
    }
    if (t == 1023) g_bsum[blockIdx.x] = sd[t];
}

__global__ void scan2_kernel() {
    __shared__ int sd[128];
    int t = threadIdx.x;
    int v = (t < NBLK) ? g_bsum[t] : 0;
    sd[t] = v;
    __syncthreads();
    #pragma unroll
    for (int off = 1; off < 128; off <<= 1) {
        int x = (t >= off) ? sd[t - off] : 0;
        __syncthreads();
        if (t >= off) sd[t] += x;
        __syncthreads();
    }
    if (t < NBLK) g_boff[t] = sd[t] - v;
    if (t == 127) g_rptr[NN] = sd[127];              // == EE
}

__global__ void scan3_kernel() {
    int i = blockIdx.x * blockDim.x + threadIdx.x;
    if (i < NN) g_rptr[i] += g_boff[i >> 10];
}

__global__ void scatter_kernel(const int* __restrict__ row, const int* __restrict__ col) {
    int i = blockIdx.x * blockDim.x + threadIdx.x;
    if (i < EE) {
        int r = row[i];
        int p = g_rptr[r] + atomicAdd(&g_fill[r], 1);
        g_cols[p] = col[i];
    }
}

// ---------------- FC first (commutes with propagation): Z = feat @ W^T ----------------
// warp per node; W (40x128 = 20KB) staged in shared as float4
__global__ void gemm_kernel(const float* __restrict__ feat,
                            const float* __restrict__ W,
                            float* __restrict__ out) {
    __shared__ float4 Ws[CC * 32];
    int t = threadIdx.x;
    for (int i = t; i < CC * 32; i += 256)
        Ws[i] = ((const float4*)W)[i];
    __syncthreads();
    int warp = t >> 5, lane = t & 31;
    int node = blockIdx.x * 8 + warp;
    if (node >= NN) return;
    float4 h4 = ((const float4*)feat)[node * 32 + lane];
    float y0 = 0.f, y1 = 0.f;
    #pragma unroll
    for (int c = 0; c < CC; c++) {
        float4 w4 = Ws[c * 32 + lane];
        float p = h4.x * w4.x + h4.y * w4.y + h4.z * w4.z + h4.w * w4.w;
        p += __shfl_xor_sync(0xffffffffu, p, 16);
        p += __shfl_xor_sync(0xffffffffu, p, 8);
        p += __shfl_xor_sync(0xffffffffu, p, 4);
        p += __shfl_xor_sync(0xffffffffu, p, 2);
        p += __shfl_xor_sync(0xffffffffu, p, 1);
        if (lane == (c & 31)) { if (c < 32) y0 = p; else y1 = p; }
    }
    out[node * CC + lane] = y0;
    if (lane < 8) out[node * CC + 32 + lane] = y1;
}

// ---------------- propagation: h <- 0.5*h + 0.5*(S h), warp per row ----------------
// lane l covers feature l; lanes 0..7 additionally cover feature 32+l.
// LAST=1 fuses bias + LayerNorm and writes the final output.
template <int LAST>
__global__ void spmm_kernel(const float* __restrict__ hin,
                            float* __restrict__ hout,
                            const float* __restrict__ bias,
                            const float* __restrict__ gamma,
                            const float* __restrict__ beta,
                            float* __restrict__ dout) {
    int row  = blockIdx.x * 8 + (threadIdx.x >> 5);
    int lane = threadIdx.x & 31;
    if (row >= NN) return;
    bool lo8 = lane < 8;
    float dr = g_dinv[row];
    int s = g_rptr[row], e = g_rptr[row + 1];
    float a0 = 0.f, a1 = 0.f;
    for (int i = s; i < e; ++i) {
        int c = g_cols[i];
        float w = dr * g_dinv[c];
        const float* hp = hin + c * CC;
        a0 += w * __ldcg(hp + lane);
        if (lo8) a1 += w * __ldcg(hp + 32 + lane);
    }
    float h0 = hin[row * CC + lane];
    float h1 = lo8 ? hin[row * CC + 32 + lane] : 0.f;
    float sc = 0.5f + 0.5f * dr * dr;                // residual + self-loop term
    float r0 = h0 * sc + 0.5f * a0;
    float r1 = h1 * sc + 0.5f * a1;
    if (!LAST) {
        hout[row * CC + lane] = r0;
        if (lo8) hout[row * CC + 32 + lane] = r1;
    } else {
        r0 += bias[lane];
        if (lo8) r1 += bias[32 + lane];
        float s1 = r0 + (lo8 ? r1 : 0.f);
        float s2 = r0 * r0 + (lo8 ? r1 * r1 : 0.f);
        #pragma unroll
        for (int o = 16; o; o >>= 1) {
            s1 += __shfl_xor_sync(0xffffffffu, s1, o);
            s2 += __shfl_xor_sync(0xffffffffu, s2, o);
        }
        float mu   = s1 * (1.0f / CC);
        float var  = s2 * (1.0f / CC) - mu * mu;
        float rstd = rsqrtf(var + LN_EPS);
        dout[row * CC + lane] = (r0 - mu) * rstd * gamma[lane] + beta[lane];
        if (lo8)
            dout[row * CC + 32 + lane] = (r1 - mu) * rstd * gamma[32 + lane] + beta[32 + lane];
    }
}

// ---------------- launch ----------------
extern "C" void kernel_launch(void* const* d_in, const int* in_sizes, int n_in,
                              void* d_out, int out_size) {
    const float* feat  = (const float*)d_in[0];
    const int*   row   = (const int*)d_in[1];
    const int*   col   = (const int*)d_in[2];
    const float* W     = (const float*)d_in[3];
    const float* bias  = (const float*)d_in[4];
    const float* gamma = (const float*)d_in[5];
    const float* beta  = (const float*)d_in[6];
    float* out = (float*)d_out;

    float *pA = nullptr, *pB = nullptr;
    cudaGetSymbolAddress((void**)&pA, g_bufA);
    cudaGetSymbolAddress((void**)&pB, g_bufB);

    zero_kernel<<<(NN + 255) / 256, 256>>>();
    hist_kernel<<<(EE + 255) / 256, 256>>>(row);
    scan1_kernel<<<NBLK, 1024>>>();
    scan2_kernel<<<1, 128>>>();
    scan3_kernel<<<(NN + 255) / 256, 256>>>();
    scatter_kernel<<<(EE + 255) / 256, 256>>>(row, col);

    int sblocks = (NN + 7) / 8;
    gemm_kernel<<<sblocks, 256>>>(feat, W, pA);
    spmm_kernel<0><<<sblocks, 256>>>(pA, pB, nullptr, nullptr, nullptr, nullptr);
    spmm_kernel<0><<<sblocks, 256>>>(pB, pA, nullptr, nullptr, nullptr, nullptr);
    spmm_kernel<0><<<sblocks, 256>>>(pA, pB, nullptr, nullptr, nullptr, nullptr);
    spmm_kernel<1><<<sblocks, 256>>>(pB, pA, bias, gamma, beta, out);
}

// round 2
// speedup vs baseline: 1.5688x; 1.5688x over previous
#include <cuda_runtime.h>
#include <cuda_bf16.h>

#define NN 100000
#define EE 1600000
#define CC 40
#define NBLK 98          // ceil(NN/1024)
#define LN_EPS 1e-5f

// ---------------- device scratch ----------------
__device__ int    g_cnt[NN];
__device__ int    g_rptr[NN];        // chunk-local exclusive scan
__device__ int    g_bsum[NBLK];
__device__ int    g_boff[NBLK];
__device__ int    g_cols[EE];
__device__ float  g_dinv[NN];        // 1/sqrt(deg+1)
__device__ float  g_w[NN];           // 1/(deg+1)
__device__ float  g_sqd[NN];         // sqrt(deg+1)
__device__ float4 g_bufA[NN * 10];
__device__ float4 g_bufB[NN * 10];

__device__ __forceinline__ int rptr_final(int r) {
    return g_rptr[r] + g_boff[r >> 10];
}

// ---------------- CSR build ----------------
__global__ void hist_kernel(const int4* __restrict__ row4) {
    int i = blockIdx.x * blockDim.x + threadIdx.x;
    if (i < EE / 4) {
        int4 r = row4[i];
        atomicAdd(&g_cnt[r.x], 1);
        atomicAdd(&g_cnt[r.y], 1);
        atomicAdd(&g_cnt[r.z], 1);
        atomicAdd(&g_cnt[r.w], 1);
    }
}

// 1024-thread chunk scan (warp shuffles); also emits dinv/w/sqd
__global__ void scan1_kernel() {
    __shared__ int wsum[32];
    int t = threadIdx.x;
    int i = blockIdx.x * 1024 + t;
    int lane = t & 31, w = t >> 5;
    int v = (i < NN) ? g_cnt[i] : 0;
    int x = v;
    #pragma unroll
    for (int o = 1; o < 32; o <<= 1) {
        int y = __shfl_up_sync(0xffffffffu, x, o);
        if (lane >= o) x += y;
    }
    if (lane == 31) wsum[w] = x;
    __syncthreads();
    if (w == 0) {
        int s = wsum[lane];
        #pragma unroll
        for (int o = 1; o < 32; o <<= 1) {
            int y = __shfl_up_sync(0xffffffffu, s, o);
            if (lane >= o) s += y;
        }
        wsum[lane] = s;
    }
    __syncthreads();
    int incl = x + (w > 0 ? wsum[w - 1] : 0);
    if (i < NN) {
        g_rptr[i] = incl - v;
        float df = (float)v + 1.0f;
        g_dinv[i] = rsqrtf(df);
        g_w[i]    = 1.0f / df;
        g_sqd[i]  = sqrtf(df);
    }
    if (t == 1023) g_bsum[blockIdx.x] = incl;
}

__global__ void scan2_kernel() {
    __shared__ int wsum[4];
    int t = threadIdx.x, lane = t & 31, w = t >> 5;
    int v = (t < NBLK) ? g_bsum[t] : 0;
    int x = v;
    #pragma unroll
    for (int o = 1; o < 32; o <<= 1) {
        int y = __shfl_up_sync(0xffffffffu, x, o);
        if (lane >= o) x += y;
    }
    if (lane == 31) wsum[w] = x;
    __syncthreads();
    int pre = 0;
    for (int j = 0; j < w; j++) pre += wsum[j];
    if (t < NBLK) g_boff[t] = pre + x - v;
}

// atomic-countdown scatter: reuses g_cnt as per-row cursor (order-free)
__global__ void scatter_kernel(const int4* __restrict__ row4, const int4* __restrict__ col4) {
    int i = blockIdx.x * blockDim.x + threadIdx.x;
    if (i < EE / 4) {
        int4 r = row4[i];
        int4 c = col4[i];
        int p;
        p = rptr_final(r.x) + atomicAdd(&g_cnt[r.x], -1) - 1; g_cols[p] = c.x;
        p = rptr_final(r.y) + atomicAdd(&g_cnt[r.y], -1) - 1; g_cols[p] = c.y;
        p = rptr_final(r.z) + atomicAdd(&g_cnt[r.z], -1) - 1; g_cols[p] = c.z;
        p = rptr_final(r.w) + atomicAdd(&g_cnt[r.w], -1) - 1; g_cols[p] = c.w;
    }
}

// ---------------- tiled GEMM: s0 = dinv ⊙ (feat @ W^T) ----------------
// block = 256 threads, 32 nodes/block. thread t: node = t&31, class-group = t>>5 (5 classes)
__global__ void gemm_kernel(const float4* __restrict__ feat4,
                            const float4* __restrict__ W4,
                            float* __restrict__ out) {
    __shared__ float4 fs[32 * 33];   // 32 rows x 32 f4, stride 33 (conflict-free)
    __shared__ float4 ws[40 * 32];
    int t = threadIdx.x;
    int n0 = blockIdx.x * 32;
    for (int i = t; i < 32 * 32; i += 256) {
        int r = i >> 5, k4 = i & 31;
        fs[r * 33 + k4] = feat4[(n0 + r) * 32 + k4];
    }
    for (int i = t; i < 40 * 32; i += 256)
        ws[i] = W4[i];
    __syncthreads();

    int n = t & 31;
    int cg = t >> 5;                  // 0..7 -> classes cg*5 .. cg*5+4
    const float4* fr = &fs[n * 33];
    const float4* wr = &ws[cg * 5 * 32];
    float acc[5] = {0.f, 0.f, 0.f, 0.f, 0.f};
    #pragma unroll 8
    for (int k4 = 0; k4 < 32; k4++) {
        float4 f = fr[k4];
        #pragma unroll
        for (int j = 0; j < 5; j++) {
            float4 wv = wr[j * 32 + k4];
            acc[j] += f.x * wv.x + f.y * wv.y + f.z * wv.z + f.w * wv.w;
        }
    }
    float dv = g_dinv[n0 + n];
    float* op = out + (n0 + n) * CC + cg * 5;
    #pragma unroll
    for (int j = 0; j < 5; j++) op[j] = acc[j] * dv;
}

// ---------------- propagation in scaled space ----------------
// s' = 0.5*s + 0.5*w*(A s + s);  warp/row; lanes in 3 groups of 10, float4 gathers
template <int LAST>
__global__ void spmm_kernel(const float4* __restrict__ hin,
                            float4* __restrict__ hout,
                            const float4* __restrict__ bias4,
                            const float4* __restrict__ gamma4,
                            const float4* __restrict__ beta4,
                            float4* __restrict__ dout) {
    int lane = threadIdx.x & 31;
    int row = blockIdx.x * 8 + (threadIdx.x >> 5);
    int sub = lane / 10;              // 0,1,2 active; 3 = lanes 30,31 idle
    int fl  = lane - sub * 10;
    bool act = sub < 3;

    int s = g_rptr[row] + g_boff[row >> 10];
    int e = (row + 1 == NN) ? EE : (g_rptr[row + 1] + g_boff[(row + 1) >> 10]);

    float4 acc = make_float4(0.f, 0.f, 0.f, 0.f);
    #pragma unroll 2
    for (int i = s; i < e; i += 3) {
        int ei = i + sub;
        bool p = act && (ei < e);
        if (p) {
            int c = __ldg(&g_cols[ei]);
            float4 v = __ldcg(&hin[c * 10 + fl]);
            acc.x += v.x; acc.y += v.y; acc.z += v.z; acc.w += v.w;
        }
    }
    // combine the 3 edge-groups into lanes 0..9
    float4 b1, b2;
    b1.x = __shfl_down_sync(0xffffffffu, acc.x, 10);
    b1.y = __shfl_down_sync(0xffffffffu, acc.y, 10);
    b1.z = __shfl_down_sync(0xffffffffu, acc.z, 10);
    b1.w = __shfl_down_sync(0xffffffffu, acc.w, 10);
    b2.x = __shfl_down_sync(0xffffffffu, acc.x, 20);
    b2.y = __shfl_down_sync(0xffffffffu, acc.y, 20);
    b2.z = __shfl_down_sync(0xffffffffu, acc.z, 20);
    b2.w = __shfl_down_sync(0xffffffffu, acc.w, 20);
    acc.x += b1.x + b2.x; acc.y += b1.y + b2.y;
    acc.z += b1.z + b2.z; acc.w += b1.w + b2.w;

    float p1 = 0.f, p2 = 0.f;
    float4 r;
    if (lane < 10) {
        float4 sr = hin[row * 10 + lane];
        float wv = g_w[row];
        r.x = 0.5f * sr.x + 0.5f * wv * (acc.x + sr.x);
        r.y = 0.5f * sr.y + 0.5f * wv * (acc.y + sr.y);
        r.z = 0.5f * sr.z + 0.5f * wv * (acc.z + sr.z);
        r.w = 0.5f * sr.w + 0.5f * wv * (acc.w + sr.w);
        if (!LAST) {
            hout[row * 10 + lane] = r;
        } else {
            float q = g_sqd[row];          // unscale: h = s * sqrt(deg+1)
            float4 bb = bias4[lane];
            r.x = r.x * q + bb.x;
            r.y = r.y * q + bb.y;
            r.z = r.z * q + bb.z;
            r.w = r.w * q + bb.w;
            p1 = r.x + r.y + r.z + r.w;
            p2 = r.x * r.x + r.y * r.y + r.z * r.z + r.w * r.w;
        }
    }
    if (LAST) {
        #pragma unroll
        for (int o = 16; o; o >>= 1) {
            p1 += __shfl_xor_sync(0xffffffffu, p1, o);
            p2 += __shfl_xor_sync(0xffffffffu, p2, o);
        }
        if (lane < 10) {
            float mu   = p1 * (1.0f / CC);
            float rstd = rsqrtf(p2 * (1.0f / CC) - mu * mu + LN_EPS);
            float4 g = gamma4[lane], be = beta4[lane];
            float4 o;
            o.x = (r.x - mu) * rstd * g.x + be.x;
            o.y = (r.y - mu) * rstd * g.y + be.y;
            o.z = (r.z - mu) * rstd * g.z + be.z;
            o.w = (r.w - mu) * rstd * g.w + be.w;
            dout[row * 10 + lane] = o;
        }
    }
}

// ---------------- launch ----------------
extern "C" void kernel_launch(void* const* d_in, const int* in_sizes, int n_in,
                              void* d_out, int out_size) {
    const float* feat  = (const float*)d_in[0];
    const int*   row   = (const int*)d_in[1];
    const int*   col   = (const int*)d_in[2];
    const float* W     = (const float*)d_in[3];
    const float* bias  = (const float*)d_in[4];
    const float* gamma = (const float*)d_in[5];
    const float* beta  = (const float*)d_in[6];

    void *pCnt = nullptr, *pA = nullptr, *pB = nullptr;
    cudaGetSymbolAddress(&pCnt, g_cnt);
    cudaGetSymbolAddress(&pA, g_bufA);
    cudaGetSymbolAddress(&pB, g_bufB);
    float4* bufA = (float4*)pA;
    float4* bufB = (float4*)pB;

    cudaMemsetAsync(pCnt, 0, NN * sizeof(int));
    hist_kernel<<<(EE / 4 + 255) / 256, 256>>>((const int4*)row);
    scan1_kernel<<<NBLK, 1024>>>();
    scan2_kernel<<<1, 128>>>();
    scatter_kernel<<<(EE / 4 + 255) / 256, 256>>>((const int4*)row, (const int4*)col);

    gemm_kernel<<<NN / 32, 256>>>((const float4*)feat, (const float4*)W, (float*)pA);

    int sblocks = NN / 8;
    spmm_kernel<0><<<sblocks, 256>>>(bufA, bufB, nullptr, nullptr, nullptr, nullptr);
    spmm_kernel<0><<<sblocks, 256>>>(bufB, bufA, nullptr, nullptr, nullptr, nullptr);
    spmm_kernel<0><<<sblocks, 256>>>(bufA, bufB, nullptr, nullptr, nullptr, nullptr);
    spmm_kernel<1><<<sblocks, 256>>>(bufB, bufA,
                                     (const float4*)bias, (const float4*)gamma,
                                     (const float4*)beta, (float4*)d_out);
}